// round 1
// baseline (speedup 1.0000x reference)
#include <cuda_runtime.h>
#include <math.h>
#include <stdint.h>

// Problem constants
#define BATCH 4
#define NQ    2048
#define NCTX  1024
#define DIMM  1024
#define HEADS 16
#define DHEAD 64
#define FFI   4096   // FF_INNER

// ---------------------------------------------------------------------------
// Scratch (static device globals; allocation-free at runtime)
// ---------------------------------------------------------------------------
__device__ float g_xn  [(size_t)BATCH * NQ   * DIMM];        // 32 MB
__device__ float g_cn  [(size_t)BATCH * NCTX * DIMM];        // 16 MB
__device__ float g_q   [(size_t)BATCH * NQ   * DIMM];        // 32 MB
__device__ float g_kv  [(size_t)BATCH * NCTX * 2 * DHEAD];   //  2 MB
__device__ float g_attn[(size_t)BATCH * NQ   * DIMM];        // 32 MB
__device__ float g_ff1 [(size_t)BATCH * NQ   * 2 * FFI];     // 256 MB
__device__ float g_act [(size_t)BATCH * NQ   * FFI];         // 128 MB

// ---------------------------------------------------------------------------
// LayerNorm: one block per row of 1024
// ---------------------------------------------------------------------------
__global__ __launch_bounds__(256) void ln_kernel(
    const float* __restrict__ x, const float* __restrict__ g,
    const float* __restrict__ b, float* __restrict__ y, int cols)
{
    int row = blockIdx.x;
    const float* xr = x + (size_t)row * cols;
    float*       yr = y + (size_t)row * cols;

    float s = 0.f, s2 = 0.f;
    for (int c = threadIdx.x; c < cols; c += blockDim.x) {
        float v = xr[c]; s += v; s2 += v * v;
    }
    __shared__ float red[64];
    #pragma unroll
    for (int o = 16; o; o >>= 1) {
        s  += __shfl_xor_sync(0xffffffffu, s,  o);
        s2 += __shfl_xor_sync(0xffffffffu, s2, o);
    }
    int w = threadIdx.x >> 5, l = threadIdx.x & 31;
    if (l == 0) { red[w] = s; red[32 + w] = s2; }
    __syncthreads();
    int nw = blockDim.x >> 5;
    if (w == 0) {
        s  = (l < nw) ? red[l]      : 0.f;
        s2 = (l < nw) ? red[32 + l] : 0.f;
        #pragma unroll
        for (int o = 16; o; o >>= 1) {
            s  += __shfl_xor_sync(0xffffffffu, s,  o);
            s2 += __shfl_xor_sync(0xffffffffu, s2, o);
        }
        if (l == 0) { red[0] = s; red[1] = s2; }
    }
    __syncthreads();
    float mu  = red[0] / cols;
    float var = red[1] / cols - mu * mu;
    float inv = rsqrtf(var + 1e-5f);
    for (int c = threadIdx.x; c < cols; c += blockDim.x)
        yr[c] = (xr[c] - mu) * inv * g[c] + b[c];
}

// ---------------------------------------------------------------------------
// Classic 128x128x8 register-blocked SGEMM, 8x8 microtile, 256 threads.
// All dims are multiples of (128, 128, 8) in this problem -> no bounds checks.
// ---------------------------------------------------------------------------
template <bool ADD>
__global__ __launch_bounds__(256) void sgemm128(
    const float* __restrict__ A, const float* __restrict__ Bm,
    float* __restrict__ C, int M, int Nn, int K)
{
    __shared__ float As[8][128];
    __shared__ float Bs[8][128];

    int bx = blockIdx.x, by = blockIdx.y;
    int tid = threadIdx.x;
    int tr = tid >> 4, tc = tid & 15;

    float acc[8][8] = {};

    int arow = tid >> 1, acol = (tid & 1) * 4;
    int brow = tid >> 5, bcol = (tid & 31) * 4;

    const float* Ab = A  + (size_t)(by * 128) * K;
    const float* Bb = Bm + bx * 128;

    for (int k0 = 0; k0 < K; k0 += 8) {
        float4 av = *(const float4*)(Ab + (size_t)arow * K + k0 + acol);
        As[acol + 0][arow] = av.x;
        As[acol + 1][arow] = av.y;
        As[acol + 2][arow] = av.z;
        As[acol + 3][arow] = av.w;
        float4 bv = *(const float4*)(Bb + (size_t)(k0 + brow) * Nn + bcol);
        *(float4*)(&Bs[brow][bcol]) = bv;
        __syncthreads();

        #pragma unroll
        for (int kk = 0; kk < 8; kk++) {
            float ra[8], rb[8];
            #pragma unroll
            for (int i = 0; i < 8; i++) ra[i] = As[kk][tr * 8 + i];
            #pragma unroll
            for (int j = 0; j < 8; j++) rb[j] = Bs[kk][tc * 8 + j];
            #pragma unroll
            for (int i = 0; i < 8; i++)
                #pragma unroll
                for (int j = 0; j < 8; j++)
                    acc[i][j] = fmaf(ra[i], rb[j], acc[i][j]);
        }
        __syncthreads();
    }

    #pragma unroll
    for (int i = 0; i < 8; i++) {
        size_t cbase = (size_t)(by * 128 + tr * 8 + i) * Nn + bx * 128 + tc * 8;
        #pragma unroll
        for (int j = 0; j < 8; j += 4) {
            float4* cp = (float4*)(C + cbase + j);
            float4 v = make_float4(acc[i][j], acc[i][j+1], acc[i][j+2], acc[i][j+3]);
            if (ADD) {
                float4 o = *cp;
                v.x += o.x; v.y += o.y; v.z += o.z; v.w += o.w;
            }
            *cp = v;
        }
    }
}

// ---------------------------------------------------------------------------
// Flash-style attention. K/V are SHARED ACROSS HEADS (multi-query):
//   q:   [B, NQ, HEADS*64]   (row = b*NQ+n, col = h*64+d), pre-GEMM output
//   kv:  [B, NCTX, 128]      (k = cols 0..63, v = cols 64..127)
//   out: [B, NQ, HEADS*64]
// Block: 64 q-rows of one (b,h); loops over 16 key tiles of 64.
// K-tile smem buffer is reused to hold P after S is computed (saves 16KB).
// Dynamic smem: 2*64*65 + 64*64 + 192 floats = 50432 B.
// ---------------------------------------------------------------------------
__global__ __launch_bounds__(256) void attn_kernel(
    const float* __restrict__ q, const float* __restrict__ kv,
    float* __restrict__ out)
{
    extern __shared__ float sm[];
    float (*q_s)[65]  = (float(*)[65]) sm;                 // 64x65
    float (*kp_s)[65] = (float(*)[65])(sm + 64 * 65);      // 64x65 (K, then P)
    float (*v_s)[64]  = (float(*)[64])(sm + 2 * 64 * 65);  // 64x64
    float* m_s = sm + 2 * 64 * 65 + 64 * 64;
    float* l_s = m_s + 64;
    float* c_s = l_s + 64;

    int bh = blockIdx.y;
    int b  = bh >> 4, h = bh & 15;
    int n0 = blockIdx.x * 64;
    int tid = threadIdx.x;
    int ty = tid >> 4, tx = tid & 15;
    const float scale = 0.125f;  // 64^-0.5

    for (int idx = tid; idx < 64 * 64; idx += 256) {
        int r = idx >> 6, d = idx & 63;
        q_s[r][d] = q[(size_t)(b * NQ + n0 + r) * DIMM + h * 64 + d] * scale;
    }
    if (tid < 64) { m_s[tid] = -1e30f; l_s[tid] = 0.f; }
    float acc[4][4] = {};
    __syncthreads();

    for (int jt = 0; jt < NCTX; jt += 64) {
        // load K/V tile
        for (int idx = tid; idx < 64 * 64; idx += 256) {
            int r = idx >> 6, d = idx & 63;
            const float* kvp = kv + (size_t)(b * NCTX + jt + r) * 128;
            kp_s[r][d] = kvp[d];
            v_s[r][d]  = kvp[64 + d];
        }
        __syncthreads();

        // S = Q K^T  (64x64), 4x4 per thread
        float sacc[4][4] = {};
        #pragma unroll
        for (int kk = 0; kk < 64; kk++) {
            float ra[4], rb[4];
            #pragma unroll
            for (int i = 0; i < 4; i++) ra[i] = q_s[ty * 4 + i][kk];
            #pragma unroll
            for (int j = 0; j < 4; j++) rb[j] = kp_s[tx * 4 + j][kk];
            #pragma unroll
            for (int i = 0; i < 4; i++)
                #pragma unroll
                for (int j = 0; j < 4; j++)
                    sacc[i][j] = fmaf(ra[i], rb[j], sacc[i][j]);
        }
        __syncthreads();   // done reading K -> buffer becomes P storage

        #pragma unroll
        for (int i = 0; i < 4; i++)
            #pragma unroll
            for (int j = 0; j < 4; j++)
                kp_s[ty * 4 + i][tx * 4 + j] = sacc[i][j];
        __syncthreads();

        // online softmax bookkeeping: one thread per row
        if (tid < 64) {
            float m_old = m_s[tid];
            float mx = m_old;
            #pragma unroll 8
            for (int c = 0; c < 64; c++) mx = fmaxf(mx, kp_s[tid][c]);
            float corr = __expf(m_old - mx);
            float sum = 0.f;
            #pragma unroll 8
            for (int c = 0; c < 64; c++) {
                float p = __expf(kp_s[tid][c] - mx);
                kp_s[tid][c] = p;
                sum += p;
            }
            m_s[tid] = mx;
            l_s[tid] = l_s[tid] * corr + sum;
            c_s[tid] = corr;
        }
        __syncthreads();

        // O = O*corr + P V
        #pragma unroll
        for (int i = 0; i < 4; i++) {
            float corr = c_s[ty * 4 + i];
            #pragma unroll
            for (int j = 0; j < 4; j++) acc[i][j] *= corr;
        }
        #pragma unroll
        for (int kk = 0; kk < 64; kk++) {
            float ra[4], rb[4];
            #pragma unroll
            for (int i = 0; i < 4; i++) ra[i] = kp_s[ty * 4 + i][kk];
            #pragma unroll
            for (int j = 0; j < 4; j++) rb[j] = v_s[kk][tx * 4 + j];
            #pragma unroll
            for (int i = 0; i < 4; i++)
                #pragma unroll
                for (int j = 0; j < 4; j++)
                    acc[i][j] = fmaf(ra[i], rb[j], acc[i][j]);
        }
        __syncthreads();
    }

    #pragma unroll
    for (int i = 0; i < 4; i++) {
        int r = ty * 4 + i;
        float invl = 1.f / l_s[r];
        #pragma unroll
        for (int j = 0; j < 4; j++)
            out[(size_t)(b * NQ + n0 + r) * DIMM + h * 64 + tx * 4 + j]
                = acc[i][j] * invl;
    }
}

// ---------------------------------------------------------------------------
// act = silu(gate) * h ; ff1 layout: [rows, 8192] with h = [:,:4096], gate = [:,4096:]
// ---------------------------------------------------------------------------
__global__ __launch_bounds__(256) void silu_mul_kernel(
    const float* __restrict__ ff1, float* __restrict__ act)
{
    size_t i = (size_t)blockIdx.x * blockDim.x + threadIdx.x;
    size_t row = i >> 12;
    int    c   = (int)(i & 4095);
    float h = ff1[row * 8192 + c];
    float g = ff1[row * 8192 + 4096 + c];
    float sg = g / (1.f + __expf(-g));
    act[i] = sg * h;
}

// ---------------------------------------------------------------------------
// Launch
// ---------------------------------------------------------------------------
static float* sym_addr(const void* sym) {
    void* p = nullptr;
    cudaGetSymbolAddress(&p, sym);
    return (float*)p;
}

extern "C" void kernel_launch(void* const* d_in, const int* in_sizes, int n_in,
                              void* d_out, int out_size)
{
    const float* x      = (const float*)d_in[0];
    const float* ctx    = (const float*)d_in[1];
    const float* ln_g   = (const float*)d_in[2];
    const float* ln_b   = (const float*)d_in[3];
    const float* cln_g  = (const float*)d_in[4];
    const float* cln_b  = (const float*)d_in[5];
    const float* Wq     = (const float*)d_in[6];
    const float* Wkv    = (const float*)d_in[7];
    const float* Wo     = (const float*)d_in[8];
    const float* Wff1   = (const float*)d_in[9];
    const float* Wff2   = (const float*)d_in[10];
    float* out = (float*)d_out;

    float* xn   = sym_addr(g_xn);
    float* cn   = sym_addr(g_cn);
    float* qb   = sym_addr(g_q);
    float* kvb  = sym_addr(g_kv);
    float* attn = sym_addr(g_attn);
    float* ff1  = sym_addr(g_ff1);
    float* act  = sym_addr(g_act);

    const int ATTN_SMEM = (2 * 64 * 65 + 64 * 64 + 192) * 4;  // 50432 B
    cudaFuncSetAttribute(attn_kernel,
                         cudaFuncAttributeMaxDynamicSharedMemorySize, ATTN_SMEM);

    // 1) LayerNorms
    ln_kernel<<<BATCH * NQ,   256>>>(x,   ln_g,  ln_b,  xn, DIMM);
    ln_kernel<<<BATCH * NCTX, 256>>>(ctx, cln_g, cln_b, cn, DIMM);

    // 2) Q = xn @ Wq   [8192 x 1024 x 1024]
    sgemm128<false><<<dim3(DIMM / 128, BATCH * NQ / 128), 256>>>(
        xn, Wq, qb, BATCH * NQ, DIMM, DIMM);

    // 3) KV = cn @ Wkv [4096 x 128 x 1024]
    sgemm128<false><<<dim3(1, BATCH * NCTX / 128), 256>>>(
        cn, Wkv, kvb, BATCH * NCTX, 128, DIMM);

    // 4) attention (multi-query flash)
    attn_kernel<<<dim3(NQ / 64, BATCH * HEADS), 256, ATTN_SMEM>>>(qb, kvb, attn);

    // 5) FF1 = xn @ Wff1 [8192 x 8192 x 1024]
    sgemm128<false><<<dim3(2 * FFI / 128, BATCH * NQ / 128), 256>>>(
        xn, Wff1, ff1, BATCH * NQ, 2 * FFI, DIMM);

    // 6) act = silu(gate) * h
    {
        size_t total = (size_t)BATCH * NQ * FFI;
        silu_mul_kernel<<<(unsigned)(total / 256), 256>>>(ff1, act);
    }

    // 7) out = attn @ Wo [8192 x 1024 x 1024]
    sgemm128<false><<<dim3(DIMM / 128, BATCH * NQ / 128), 256>>>(
        attn, Wo, out, BATCH * NQ, DIMM, DIMM);

    // 8) out += act @ Wff2 [8192 x 1024 x 4096]
    sgemm128<true><<<dim3(DIMM / 128, BATCH * NQ / 128), 256>>>(
        act, Wff2, out, BATCH * NQ, DIMM, FFI);
}